// round 4
// baseline (speedup 1.0000x reference)
#include <cuda_runtime.h>
#include <cstdint>
#include <cstddef>

// ---------------- sizes ----------------
#define MROWS 51200   // B*N*S
#define FEAT  2104
#define KP1   2176    // padded K for GEMM1 (68*32)
#define GP    2304    // padded hidden (72*32, 18*128)
#define TOK   1024
#define BNN   1024
#define SMEM_BYTES 73728   // 2 stages * (A 18432 + B 18432)

// ---------------- scratch ----------------
__device__ float g_A   [(size_t)MROWS * KP1];
__device__ float g_W1T [(size_t)GP    * KP1];
__device__ float g_W2T [(size_t)TOK   * GP];
__device__ float g_hbar[(size_t)BNN   * GP];
__device__ float g_cnt [BNN];
__device__ int   g_ridx[MROWS];
__device__ int   g_active;
__device__ int   g_mask_kind;   // 0=int8/bool, 1=int32, 2=float32

// ---------------- helpers ----------------
__device__ __forceinline__ float rnd_tf32(float x){
    uint32_t r; asm("cvt.rna.tf32.f32 %0, %1;" : "=r"(r) : "f"(x));
    return __uint_as_float(r);
}
__device__ __forceinline__ uint32_t smem_u32(const void* p){
    uint32_t a;
    asm("{ .reg .u64 t; cvta.to.shared.u64 t, %1; cvt.u32.u64 %0, t; }" : "=r"(a) : "l"(p));
    return a;
}
__device__ __forceinline__ int mask_at(const void* m, int i){
    int k = g_mask_kind;
    if (k == 0) return ((const unsigned char*)m)[i] != 0;
    if (k == 1) return ((const int*)m)[i] != 0;
    return ((const float*)m)[i] != 0.f;
}
#define CP_ASYNC16(s, g) asm volatile("cp.async.cg.shared.global [%0], [%1], 16;" :: "r"(s), "l"(g) : "memory")
#define CP_COMMIT()      asm volatile("cp.async.commit_group;" ::: "memory")
#define CP_WAIT1()       asm volatile("cp.async.wait_group 1;" ::: "memory")
#define CP_WAIT0()       asm volatile("cp.async.wait_group 0;" ::: "memory")

__device__ __forceinline__ void mma8(float* d, const uint32_t* a, const uint32_t* b){
    asm volatile(
        "mma.sync.aligned.m16n8k8.row.col.f32.tf32.tf32.f32 "
        "{%0,%1,%2,%3}, {%4,%5,%6,%7}, {%8,%9}, {%0,%1,%2,%3};"
        : "+f"(d[0]), "+f"(d[1]), "+f"(d[2]), "+f"(d[3])
        : "r"(a[0]), "r"(a[1]), "r"(a[2]), "r"(a[3]), "r"(b[0]), "r"(b[1]));
}

// ---------------- mask dtype detection ----------------
// Scans first 12800 words (= 51200 bytes; in-bounds for int8/int32/float32 buffers).
// int32 mask: every word is 0 or 1. float32 mask: every word is 0 or 0x3F800000.
// packed bytes: words contain multi-byte patterns -> neither predicate holds.
__global__ void detect_mask_k(const unsigned* __restrict__ m){
    __shared__ int not_i32, not_f32;
    if (threadIdx.x == 0){ not_i32 = 0; not_f32 = 0; }
    __syncthreads();
    for (int i = threadIdx.x; i < 12800; i += 256){
        unsigned v = m[i];
        if (v > 1u) not_i32 = 1;
        if (v != 0u && v != 0x3F800000u) not_f32 = 1;
    }
    __syncthreads();
    if (threadIdx.x == 0)
        g_mask_kind = (!not_i32) ? 1 : ((!not_f32) ? 2 : 0);
}

// ---------------- compaction (deterministic order) ----------------
__global__ void compact_k(const void* __restrict__ mask){
    __shared__ int wsum[8];
    __shared__ int base;
    int tid = threadIdx.x, wid = tid >> 5, lane = tid & 31;
    if (tid == 0) base = 0;
    __syncthreads();
    for (int start = 0; start < MROWS; start += 256){
        int i = start + tid;
        int m = mask_at(mask, i);
        unsigned bal = __ballot_sync(0xffffffffu, m);
        int pre = __popc(bal & ((1u << lane) - 1u));
        if (lane == 0) wsum[wid] = __popc(bal);
        __syncthreads();
        int woff = 0, tot = 0;
        #pragma unroll
        for (int w = 0; w < 8; w++){ if (w < wid) woff += wsum[w]; tot += wsum[w]; }
        if (m) g_ridx[base + woff + pre] = i;
        __syncthreads();
        if (tid == 0) base += tot;
        __syncthreads();
    }
    if (tid == 0) g_active = base;
}

// ---------------- pack kernels ----------------
__global__ void pack_A_k(const float* __restrict__ emb, const float* __restrict__ vis,
                         const float* __restrict__ bbox, const float* __restrict__ kp){
    int ci = blockIdx.x;
    if (ci >= g_active) return;
    int r = g_ridx[ci];
    for (int c = threadIdx.x; c < KP1; c += 256){
        float v;
        if (c < 2048)       v = emb[(size_t)r * 2048 + c];
        else if (c == 2048) v = vis[r];
        else if (c < 2053)  v = bbox[(size_t)r * 4 + (c - 2049)];
        else if (c < 2104)  v = kp[(size_t)r * 51 + (c - 2053)];
        else                v = 0.f;
        g_A[(size_t)ci * KP1 + c] = rnd_tf32(v);
    }
}
__global__ void pack_W1_k(const float* __restrict__ W1){
    uint32_t i = blockIdx.x * 256u + threadIdx.x;
    if (i >= (uint32_t)GP * KP1) return;
    uint32_t g = i / KP1, f = i % KP1;
    float v = (g < FEAT && f < FEAT) ? W1[(size_t)f * FEAT + g] : 0.f;
    g_W1T[i] = rnd_tf32(v);
}
__global__ void pack_W2_k(const float* __restrict__ W2){
    uint32_t i = blockIdx.x * 256u + threadIdx.x;
    if (i >= (uint32_t)TOK * GP) return;
    uint32_t t = i / GP, g = i % GP;
    float v = (g < FEAT) ? W2[(size_t)g * TOK + t] : 0.f;
    g_W2T[i] = rnd_tf32(v);
}
__global__ void cnt_k(const void* __restrict__ mask){
    int bn = blockIdx.x * 256 + threadIdx.x;
    if (bn >= BNN) return;
    float s = 0.f;
    for (int j = 0; j < 50; j++) s += (float)mask_at(mask, bn * 50 + j);
    g_cnt[bn] = s;
}
__global__ void round_hbar_k(){
    uint32_t i = blockIdx.x * 256u + threadIdx.x;
    if (i < (uint32_t)BNN * GP) g_hbar[i] = rnd_tf32(g_hbar[i]);
}

// ---------------- tf32 mma.sync GEMM: CTA 128x128, K-chunk 32, 2-stage cp.async ----------------
// MODE 0: g_A(compact)[.,KP1] @ g_W1T^T -> relu(+b1), S-group reduce -> atomicAdd g_hbar
// MODE 1: g_hbar[1024,GP]     @ g_W2T^T -> (+cnt*b2)/50 -> outp
template<int MODE>
__global__ __launch_bounds__(256, 2) void gemm_tc(const float* __restrict__ bias,
                                                  float* __restrict__ outp){
    constexpr int LD  = (MODE == 0) ? KP1 : GP;
    constexpr int KCH = LD / 32;
    const float* Aq = (MODE == 0) ? g_A   : g_hbar;
    const float* Bq = (MODE == 0) ? g_W1T : g_W2T;

    int mtile = blockIdx.x, ntile = blockIdx.y;
    int active = (MODE == 0) ? g_active : BNN;
    if (mtile * 128 >= active) return;

    extern __shared__ char smem[];
    __shared__ int rbn[128];
    uint32_t sb = smem_u32(smem);

    int tid = threadIdx.x, wid = tid >> 5, lane = tid & 31;
    int warp_m = wid & 1, warp_n = wid >> 1;
    int g = lane >> 2, t4 = lane & 3;

    int srow = tid >> 1, shalf = tid & 1;
    const float* ag = Aq + (size_t)(mtile * 128 + srow) * LD + shalf * 16;
    const float* bg = Bq + (size_t)(ntile * 128 + srow) * LD + shalf * 16;
    uint32_t s_off = (uint32_t)(srow * 144 + shalf * 64);

    float d[4][4][4];
    #pragma unroll
    for (int i = 0; i < 4; i++)
        #pragma unroll
        for (int j = 0; j < 4; j++)
            #pragma unroll
            for (int k = 0; k < 4; k++) d[i][j][k] = 0.f;

    int ar0 = (warp_m * 64 + g) * 36 + t4;
    int br0 = (warp_n * 32 + g) * 36 + t4;

    {
        uint32_t sa = sb + s_off, sbb = sb + 18432 + s_off;
        #pragma unroll
        for (int j = 0; j < 4; j++){
            CP_ASYNC16(sa + j * 16, (const char*)ag + j * 16);
            CP_ASYNC16(sbb + j * 16, (const char*)bg + j * 16);
        }
        CP_COMMIT();
    }

    for (int c = 0; c < KCH; c++){
        int cur = c & 1;
        if (c + 1 < KCH){
            uint32_t off = ((c + 1) & 1) * 36864u;
            uint32_t sa = sb + off + s_off, sbb = sb + off + 18432 + s_off;
            const char* agc = (const char*)(ag + (c + 1) * 32);
            const char* bgc = (const char*)(bg + (c + 1) * 32);
            #pragma unroll
            for (int j = 0; j < 4; j++){
                CP_ASYNC16(sa + j * 16, agc + j * 16);
                CP_ASYNC16(sbb + j * 16, bgc + j * 16);
            }
            CP_COMMIT();
            CP_WAIT1();
        } else {
            CP_WAIT0();
        }
        __syncthreads();

        const uint32_t* sA = (const uint32_t*)(smem + cur * 36864);
        const uint32_t* sB = (const uint32_t*)(smem + cur * 36864 + 18432);
        #pragma unroll
        for (int s = 0; s < 4; s++){
            uint32_t a[4][4], b[4][2];
            #pragma unroll
            for (int mt = 0; mt < 4; mt++){
                int o = ar0 + mt * 576 + s * 8;
                a[mt][0] = sA[o];       a[mt][1] = sA[o + 288];
                a[mt][2] = sA[o + 4];   a[mt][3] = sA[o + 288 + 4];
            }
            #pragma unroll
            for (int nt = 0; nt < 4; nt++){
                int o = br0 + nt * 288 + s * 8;
                b[nt][0] = sB[o];       b[nt][1] = sB[o + 4];
            }
            #pragma unroll
            for (int mt = 0; mt < 4; mt++)
                #pragma unroll
                for (int nt = 0; nt < 4; nt++) mma8(d[mt][nt], a[mt], b[nt]);
        }
        __syncthreads();
    }

    // ---------------- epilogue ----------------
    if (MODE == 0){
        float bv[4][2];
        #pragma unroll
        for (int nt = 0; nt < 4; nt++){
            int colg = ntile * 128 + warp_n * 32 + nt * 8 + 2 * t4;
            bv[nt][0] = (colg     < FEAT) ? bias[colg]     : 0.f;
            bv[nt][1] = (colg + 1 < FEAT) ? bias[colg + 1] : 0.f;
        }
        if (tid < 128){
            int idx = mtile * 128 + tid;
            rbn[tid] = (idx < active) ? (g_ridx[idx] / 50) : -1;
        }
        float* st = (float*)smem;  // 128 x 132 staging
        #pragma unroll
        for (int mt = 0; mt < 4; mt++){
            int rl = warp_m * 64 + mt * 16 + g;
            #pragma unroll
            for (int nt = 0; nt < 4; nt++){
                int cl = warp_n * 32 + nt * 8 + 2 * t4;
                st[rl * 132 + cl]           = fmaxf(d[mt][nt][0] + bv[nt][0], 0.f);
                st[rl * 132 + cl + 1]       = fmaxf(d[mt][nt][1] + bv[nt][1], 0.f);
                st[(rl + 8) * 132 + cl]     = fmaxf(d[mt][nt][2] + bv[nt][0], 0.f);
                st[(rl + 8) * 132 + cl + 1] = fmaxf(d[mt][nt][3] + bv[nt][1], 0.f);
            }
        }
        __syncthreads();
        int col = tid & 127, half = tid >> 7;
        int r0 = half * 64, r1 = r0 + 64;
        int colg = ntile * 128 + col;
        float s = 0.f;
        int cur = rbn[r0];
        for (int r = r0; r < r1; r++){
            int b = rbn[r];
            if (b != cur){
                if (cur >= 0) atomicAdd(&g_hbar[(size_t)cur * GP + colg], s);
                s = 0.f; cur = b;
            }
            s += st[r * 132 + col];
        }
        if (cur >= 0) atomicAdd(&g_hbar[(size_t)cur * GP + colg], s);
    } else {
        #pragma unroll
        for (int mt = 0; mt < 4; mt++){
            int rg = mtile * 128 + warp_m * 64 + mt * 16 + g;
            float cn0 = g_cnt[rg], cn8 = g_cnt[rg + 8];
            #pragma unroll
            for (int nt = 0; nt < 4; nt++){
                int cg = ntile * 128 + warp_n * 32 + nt * 8 + 2 * t4;
                float b0 = bias[cg], b1 = bias[cg + 1];
                *(float2*)(outp + (size_t)rg * TOK + cg) =
                    make_float2((d[mt][nt][0] + cn0 * b0) * 0.02f,
                                (d[mt][nt][1] + cn0 * b1) * 0.02f);
                *(float2*)(outp + (size_t)(rg + 8) * TOK + cg) =
                    make_float2((d[mt][nt][2] + cn8 * b0) * 0.02f,
                                (d[mt][nt][3] + cn8 * b1) * 0.02f);
            }
        }
    }
}

// ---------------- launch ----------------
extern "C" void kernel_launch(void* const* d_in, const int* in_sizes, int n_in,
                              void* d_out, int out_size){
    const float* emb  = (const float*)d_in[0];
    const float* vis  = (const float*)d_in[1];
    const float* bbox = (const float*)d_in[2];
    const float* kp   = (const float*)d_in[3];
    const void*  mask = d_in[4];
    const float* W1 = (const float*)d_in[5];
    const float* b1 = (const float*)d_in[6];
    const float* W2 = (const float*)d_in[7];
    const float* b2 = (const float*)d_in[8];
    float* out = (float*)d_out;

    void* hbar_ptr = nullptr;
    cudaGetSymbolAddress(&hbar_ptr, g_hbar);
    cudaFuncSetAttribute(gemm_tc<0>, cudaFuncAttributeMaxDynamicSharedMemorySize, SMEM_BYTES);
    cudaFuncSetAttribute(gemm_tc<1>, cudaFuncAttributeMaxDynamicSharedMemorySize, SMEM_BYTES);

    detect_mask_k<<<1, 256>>>((const unsigned*)mask);
    compact_k<<<1, 256>>>(mask);
    pack_A_k <<<MROWS, 256>>>(emb, vis, bbox, kp);
    pack_W1_k<<<((uint32_t)GP * KP1 + 255) / 256, 256>>>(W1);
    pack_W2_k<<<((uint32_t)TOK * GP + 255) / 256, 256>>>(W2);
    cnt_k    <<<(BNN + 255) / 256, 256>>>(mask);
    cudaMemsetAsync(hbar_ptr, 0, (size_t)BNN * GP * sizeof(float));

    gemm_tc<0><<<dim3(MROWS / 128, GP / 128), 256, SMEM_BYTES>>>(b1, nullptr);
    round_hbar_k<<<((uint32_t)BNN * GP + 255) / 256, 256>>>();
    gemm_tc<1><<<dim3(BNN / 128, TOK / 128), 256, SMEM_BYTES>>>(b2, out);
    (void)in_sizes; (void)n_in; (void)out_size;
}

// round 5
// speedup vs baseline: 1.9331x; 1.9331x over previous
#include <cuda_runtime.h>
#include <cuda_fp16.h>
#include <cstdint>
#include <cstddef>

// ---------------- sizes ----------------
#define MROWS 51200   // B*N*S
#define FEAT  2104
#define KP1   2176    // padded K for GEMM1 (68*32)
#define GP    2304    // padded hidden (72*32, 18*128)
#define TOK   1024
#define BNN   1024
#define SMEM_BYTES 67584   // max(mainloop 40960, epilogue 128*132*4)

// ---------------- scratch ----------------
__device__ __half g_A   [(size_t)MROWS * KP1];
__device__ __half g_W1T [(size_t)GP    * KP1];
__device__ __half g_W2T [(size_t)TOK   * GP];
__device__ __half g_hbh [(size_t)BNN   * GP];
__device__ float  g_hbar[(size_t)BNN   * GP];
__device__ float  g_cnt [BNN];
__device__ int    g_ridx[MROWS];
__device__ int    g_active;
__device__ int    g_mask_kind;   // 0=int8/bool, 1=int32, 2=float32

// ---------------- helpers ----------------
__device__ __forceinline__ uint32_t smem_u32(const void* p){
    uint32_t a;
    asm("{ .reg .u64 t; cvta.to.shared.u64 t, %1; cvt.u32.u64 %0, t; }" : "=r"(a) : "l"(p));
    return a;
}
__device__ __forceinline__ int mask_at(const void* m, int i){
    int k = g_mask_kind;
    if (k == 0) return ((const unsigned char*)m)[i] != 0;
    if (k == 1) return ((const int*)m)[i] != 0;
    return ((const float*)m)[i] != 0.f;
}
#define CP_ASYNC16(s, g) asm volatile("cp.async.cg.shared.global [%0], [%1], 16;" :: "r"(s), "l"(g) : "memory")
#define CP_COMMIT()      asm volatile("cp.async.commit_group;" ::: "memory")
#define CP_WAIT1()       asm volatile("cp.async.wait_group 1;" ::: "memory")
#define CP_WAIT0()       asm volatile("cp.async.wait_group 0;" ::: "memory")

// m16n8k16 f16 -> f32
__device__ __forceinline__ void mma16(float* d, const uint32_t* a, const uint32_t* b){
    asm volatile(
        "mma.sync.aligned.m16n8k16.row.col.f32.f16.f16.f32 "
        "{%0,%1,%2,%3}, {%4,%5,%6,%7}, {%8,%9}, {%0,%1,%2,%3};"
        : "+f"(d[0]), "+f"(d[1]), "+f"(d[2]), "+f"(d[3])
        : "r"(a[0]), "r"(a[1]), "r"(a[2]), "r"(a[3]), "r"(b[0]), "r"(b[1]));
}

// ---------------- mask dtype detection ----------------
__global__ void detect_mask_k(const unsigned* __restrict__ m){
    __shared__ int not_i32, not_f32;
    if (threadIdx.x == 0){ not_i32 = 0; not_f32 = 0; }
    __syncthreads();
    for (int i = threadIdx.x; i < 12800; i += 256){
        unsigned v = m[i];
        if (v > 1u) not_i32 = 1;
        if (v != 0u && v != 0x3F800000u) not_f32 = 1;
    }
    __syncthreads();
    if (threadIdx.x == 0)
        g_mask_kind = (!not_i32) ? 1 : ((!not_f32) ? 2 : 0);
}

// ---------------- compaction (deterministic order) ----------------
__global__ void compact_k(const void* __restrict__ mask){
    __shared__ int wsum[8];
    __shared__ int base;
    int tid = threadIdx.x, wid = tid >> 5, lane = tid & 31;
    if (tid == 0) base = 0;
    __syncthreads();
    for (int start = 0; start < MROWS; start += 256){
        int i = start + tid;
        int m = mask_at(mask, i);
        unsigned bal = __ballot_sync(0xffffffffu, m);
        int pre = __popc(bal & ((1u << lane) - 1u));
        if (lane == 0) wsum[wid] = __popc(bal);
        __syncthreads();
        int woff = 0, tot = 0;
        #pragma unroll
        for (int w = 0; w < 8; w++){ if (w < wid) woff += wsum[w]; tot += wsum[w]; }
        if (m) g_ridx[base + woff + pre] = i;
        __syncthreads();
        if (tid == 0) base += tot;
        __syncthreads();
    }
    if (tid == 0) g_active = base;
}

// ---------------- pack kernels ----------------
__global__ void pack_A_k(const float* __restrict__ emb, const float* __restrict__ vis,
                         const float* __restrict__ bbox, const float* __restrict__ kp){
    int ci = blockIdx.x;
    if (ci >= g_active) return;
    int r = g_ridx[ci];
    for (int c = threadIdx.x; c < KP1; c += 256){
        float v;
        if (c < 2048)       v = emb[(size_t)r * 2048 + c];
        else if (c == 2048) v = vis[r];
        else if (c < 2053)  v = bbox[(size_t)r * 4 + (c - 2049)];
        else if (c < 2104)  v = kp[(size_t)r * 51 + (c - 2053)];
        else                v = 0.f;
        g_A[(size_t)ci * KP1 + c] = __float2half_rn(v);
    }
}
__global__ void pack_W1_k(const float* __restrict__ W1){
    uint32_t i = blockIdx.x * 256u + threadIdx.x;
    if (i >= (uint32_t)GP * KP1) return;
    uint32_t g = i / KP1, f = i % KP1;
    float v = (g < FEAT && f < FEAT) ? W1[(size_t)f * FEAT + g] : 0.f;
    g_W1T[i] = __float2half_rn(v);
}
__global__ void pack_W2_k(const float* __restrict__ W2){
    uint32_t i = blockIdx.x * 256u + threadIdx.x;
    if (i >= (uint32_t)TOK * GP) return;
    uint32_t t = i / GP, g = i % GP;
    float v = (g < FEAT) ? W2[(size_t)g * TOK + t] : 0.f;
    g_W2T[i] = __float2half_rn(v);
}
__global__ void cnt_k(const void* __restrict__ mask){
    int bn = blockIdx.x * 256 + threadIdx.x;
    if (bn >= BNN) return;
    float s = 0.f;
    for (int j = 0; j < 50; j++) s += (float)mask_at(mask, bn * 50 + j);
    g_cnt[bn] = s;
}
__global__ void round_hbar_k(){
    uint32_t i = blockIdx.x * 256u + threadIdx.x;
    if (i < (uint32_t)BNN * GP) g_hbh[i] = __float2half_rn(g_hbar[i]);
}

// ---------------- f16 mma.sync GEMM: CTA 128x128, K-chunk 32 halves, 2-stage cp.async --------
// smem tile: pitch 40 halves (80B) per row; stage block = A(10240) + B(10240) = 20480 B
// MODE 0: g_A(compact)[.,KP1] @ g_W1T^T -> relu(+b1), S-group reduce -> atomicAdd g_hbar
// MODE 1: g_hbh[1024,GP]      @ g_W2T^T -> (+cnt*b2)/50 -> outp
template<int MODE>
__global__ __launch_bounds__(256, 2) void gemm_tc(const float* __restrict__ bias,
                                                  float* __restrict__ outp){
    constexpr int LD  = (MODE == 0) ? KP1 : GP;
    constexpr int KCH = LD / 32;
    const __half* Aq = (MODE == 0) ? g_A   : g_hbh;
    const __half* Bq = (MODE == 0) ? g_W1T : g_W2T;

    int mtile = blockIdx.x, ntile = blockIdx.y;
    int active = (MODE == 0) ? g_active : BNN;
    if (mtile * 128 >= active) return;

    extern __shared__ char smem[];
    __shared__ int rbn[128];
    uint32_t sb = smem_u32(smem);

    int tid = threadIdx.x, wid = tid >> 5, lane = tid & 31;
    int warp_m = wid & 1, warp_n = wid >> 1;
    int g = lane >> 2, t4 = lane & 3;

    // staging: 2 threads per 64B row, 32B each
    int srow = tid >> 1, shalf = tid & 1;
    const __half* ag = Aq + (size_t)(mtile * 128 + srow) * LD + shalf * 16;
    const __half* bg = Bq + (size_t)(ntile * 128 + srow) * LD + shalf * 16;
    uint32_t s_off = (uint32_t)(srow * 80 + shalf * 32);

    float d[4][4][4];
    #pragma unroll
    for (int i = 0; i < 4; i++)
        #pragma unroll
        for (int j = 0; j < 4; j++)
            #pragma unroll
            for (int k = 0; k < 4; k++) d[i][j][k] = 0.f;

    // fragment base word-offsets (pitch 20 words)
    int ar0 = (warp_m * 64 + g) * 20 + t4;
    int br0 = (warp_n * 32 + g) * 20 + t4;

    {   // prologue: chunk 0 -> stage 0
        uint32_t sa = sb + s_off, sbb = sb + 10240 + s_off;
        #pragma unroll
        for (int j = 0; j < 2; j++){
            CP_ASYNC16(sa + j * 16, (const char*)ag + j * 16);
            CP_ASYNC16(sbb + j * 16, (const char*)bg + j * 16);
        }
        CP_COMMIT();
    }

    for (int c = 0; c < KCH; c++){
        int cur = c & 1;
        if (c + 1 < KCH){
            uint32_t off = ((c + 1) & 1) * 20480u;
            uint32_t sa = sb + off + s_off, sbb = sb + off + 10240 + s_off;
            const char* agc = (const char*)(ag + (c + 1) * 32);
            const char* bgc = (const char*)(bg + (c + 1) * 32);
            #pragma unroll
            for (int j = 0; j < 2; j++){
                CP_ASYNC16(sa + j * 16, agc + j * 16);
                CP_ASYNC16(sbb + j * 16, bgc + j * 16);
            }
            CP_COMMIT();
            CP_WAIT1();
        } else {
            CP_WAIT0();
        }
        __syncthreads();

        const uint32_t* sA = (const uint32_t*)(smem + cur * 20480);
        const uint32_t* sB = (const uint32_t*)(smem + cur * 20480 + 10240);
        #pragma unroll
        for (int s = 0; s < 2; s++){         // two k16 steps per 32-half chunk
            uint32_t a[4][4], b[4][2];
            #pragma unroll
            for (int mt = 0; mt < 4; mt++){
                int o = ar0 + mt * 320 + s * 8;
                a[mt][0] = sA[o];       a[mt][1] = sA[o + 160];
                a[mt][2] = sA[o + 4];   a[mt][3] = sA[o + 164];
            }
            #pragma unroll
            for (int nt = 0; nt < 4; nt++){
                int o = br0 + nt * 160 + s * 8;
                b[nt][0] = sB[o];       b[nt][1] = sB[o + 4];
            }
            #pragma unroll
            for (int mt = 0; mt < 4; mt++)
                #pragma unroll
                for (int nt = 0; nt < 4; nt++) mma16(d[mt][nt], a[mt], b[nt]);
        }
        __syncthreads();
    }

    // ---------------- epilogue (layout identical to tf32 version) ----------------
    if (MODE == 0){
        float bv[4][2];
        #pragma unroll
        for (int nt = 0; nt < 4; nt++){
            int colg = ntile * 128 + warp_n * 32 + nt * 8 + 2 * t4;
            bv[nt][0] = (colg     < FEAT) ? bias[colg]     : 0.f;
            bv[nt][1] = (colg + 1 < FEAT) ? bias[colg + 1] : 0.f;
        }
        if (tid < 128){
            int idx = mtile * 128 + tid;
            rbn[tid] = (idx < active) ? (g_ridx[idx] / 50) : -1;
        }
        float* st = (float*)smem;  // 128 x 132 staging
        #pragma unroll
        for (int mt = 0; mt < 4; mt++){
            int rl = warp_m * 64 + mt * 16 + g;
            #pragma unroll
            for (int nt = 0; nt < 4; nt++){
                int cl = warp_n * 32 + nt * 8 + 2 * t4;
                st[rl * 132 + cl]           = fmaxf(d[mt][nt][0] + bv[nt][0], 0.f);
                st[rl * 132 + cl + 1]       = fmaxf(d[mt][nt][1] + bv[nt][1], 0.f);
                st[(rl + 8) * 132 + cl]     = fmaxf(d[mt][nt][2] + bv[nt][0], 0.f);
                st[(rl + 8) * 132 + cl + 1] = fmaxf(d[mt][nt][3] + bv[nt][1], 0.f);
            }
        }
        __syncthreads();
        int col = tid & 127, half = tid >> 7;
        int r0 = half * 64, r1 = r0 + 64;
        int colg = ntile * 128 + col;
        float s = 0.f;
        int cur = rbn[r0];
        for (int r = r0; r < r1; r++){
            int b = rbn[r];
            if (b != cur){
                if (cur >= 0) atomicAdd(&g_hbar[(size_t)cur * GP + colg], s);
                s = 0.f; cur = b;
            }
            s += st[r * 132 + col];
        }
        if (cur >= 0) atomicAdd(&g_hbar[(size_t)cur * GP + colg], s);
    } else {
        #pragma unroll
        for (int mt = 0; mt < 4; mt++){
            int rg = mtile * 128 + warp_m * 64 + mt * 16 + g;
            float cn0 = g_cnt[rg], cn8 = g_cnt[rg + 8];
            #pragma unroll
            for (int nt = 0; nt < 4; nt++){
                int cg = ntile * 128 + warp_n * 32 + nt * 8 + 2 * t4;
                float b0 = bias[cg], b1 = bias[cg + 1];
                *(float2*)(outp + (size_t)rg * TOK + cg) =
                    make_float2((d[mt][nt][0] + cn0 * b0) * 0.02f,
                                (d[mt][nt][1] + cn0 * b1) * 0.02f);
                *(float2*)(outp + (size_t)(rg + 8) * TOK + cg) =
                    make_float2((d[mt][nt][2] + cn8 * b0) * 0.02f,
                                (d[mt][nt][3] + cn8 * b1) * 0.02f);
            }
        }
    }
}

// ---------------- launch ----------------
extern "C" void kernel_launch(void* const* d_in, const int* in_sizes, int n_in,
                              void* d_out, int out_size){
    const float* emb  = (const float*)d_in[0];
    const float* vis  = (const float*)d_in[1];
    const float* bbox = (const float*)d_in[2];
    const float* kp   = (const float*)d_in[3];
    const void*  mask = d_in[4];
    const float* W1 = (const float*)d_in[5];
    const float* b1 = (const float*)d_in[6];
    const float* W2 = (const float*)d_in[7];
    const float* b2 = (const float*)d_in[8];
    float* out = (float*)d_out;

    void* hbar_ptr = nullptr;
    cudaGetSymbolAddress(&hbar_ptr, g_hbar);
    cudaFuncSetAttribute(gemm_tc<0>, cudaFuncAttributeMaxDynamicSharedMemorySize, SMEM_BYTES);
    cudaFuncSetAttribute(gemm_tc<1>, cudaFuncAttributeMaxDynamicSharedMemorySize, SMEM_BYTES);

    detect_mask_k<<<1, 256>>>((const unsigned*)mask);
    compact_k<<<1, 256>>>(mask);
    pack_A_k <<<MROWS, 256>>>(emb, vis, bbox, kp);
    pack_W1_k<<<((uint32_t)GP * KP1 + 255) / 256, 256>>>(W1);
    pack_W2_k<<<((uint32_t)TOK * GP + 255) / 256, 256>>>(W2);
    cnt_k    <<<(BNN + 255) / 256, 256>>>(mask);
    cudaMemsetAsync(hbar_ptr, 0, (size_t)BNN * GP * sizeof(float));

    gemm_tc<0><<<dim3(MROWS / 128, GP / 128), 256, SMEM_BYTES>>>(b1, nullptr);
    round_hbar_k<<<((uint32_t)BNN * GP + 255) / 256, 256>>>();
    gemm_tc<1><<<dim3(BNN / 128, TOK / 128), 256, SMEM_BYTES>>>(b2, out);
    (void)in_sizes; (void)n_in; (void)out_size;
}

// round 6
// speedup vs baseline: 2.3471x; 1.2141x over previous
#include <cuda_runtime.h>
#include <cuda_fp16.h>
#include <cstdint>
#include <cstddef>

// ---------------- sizes ----------------
#define MROWS 51200   // B*N*S
#define FEAT  2104
#define KP1   2176    // padded K for GEMM1 (68*32)
#define GP    2304    // padded hidden (72*32, 18*128)
#define TOK   1024
#define BNN   1024
#define SMEM_BYTES 40960   // 2 stages * (A 10240 + B 10240); epilogue reuses (<= 33792)

// ---------------- scratch ----------------
__device__ __half g_A   [(size_t)MROWS * KP1];
__device__ __half g_W1T [(size_t)GP    * KP1];
__device__ __half g_W2T [(size_t)TOK   * GP];
__device__ __half g_hbh [(size_t)BNN   * GP];
__device__ float  g_hbar[(size_t)BNN   * GP];
__device__ float  g_cnt [BNN];
__device__ int    g_cnti[BNN];
__device__ int    g_off [BNN];
__device__ int    g_ridx[MROWS];
__device__ int    g_active;
__device__ int    g_mask_kind;   // 0=int8/bool, 1=int32, 2=float32

// ---------------- helpers ----------------
__device__ __forceinline__ uint32_t smem_u32(const void* p){
    uint32_t a;
    asm("{ .reg .u64 t; cvta.to.shared.u64 t, %1; cvt.u32.u64 %0, t; }" : "=r"(a) : "l"(p));
    return a;
}
__device__ __forceinline__ int mask_at(const void* m, int i){
    int k = g_mask_kind;
    if (k == 0) return ((const unsigned char*)m)[i] != 0;
    if (k == 1) return ((const int*)m)[i] != 0;
    return ((const float*)m)[i] != 0.f;
}
#define CP_ASYNC16(s, g) asm volatile("cp.async.cg.shared.global [%0], [%1], 16;" :: "r"(s), "l"(g) : "memory")
#define CP_COMMIT()      asm volatile("cp.async.commit_group;" ::: "memory")
#define CP_WAIT1()       asm volatile("cp.async.wait_group 1;" ::: "memory")
#define CP_WAIT0()       asm volatile("cp.async.wait_group 0;" ::: "memory")
#define LDSM_X4(r0,r1,r2,r3,addr) \
    asm volatile("ldmatrix.sync.aligned.m8n8.x4.shared.b16 {%0,%1,%2,%3}, [%4];" \
        : "=r"(r0), "=r"(r1), "=r"(r2), "=r"(r3) : "r"(addr))

// m16n8k16 f16 -> f32
__device__ __forceinline__ void mma16(float* d, const uint32_t* a, const uint32_t* b){
    asm volatile(
        "mma.sync.aligned.m16n8k16.row.col.f32.f16.f16.f32 "
        "{%0,%1,%2,%3}, {%4,%5,%6,%7}, {%8,%9}, {%0,%1,%2,%3};"
        : "+f"(d[0]), "+f"(d[1]), "+f"(d[2]), "+f"(d[3])
        : "r"(a[0]), "r"(a[1]), "r"(a[2]), "r"(a[3]), "r"(b[0]), "r"(b[1]));
}

// ---------------- mask dtype detection ----------------
__global__ void detect_mask_k(const unsigned* __restrict__ m){
    __shared__ int not_i32, not_f32;
    if (threadIdx.x == 0){ not_i32 = 0; not_f32 = 0; }
    __syncthreads();
    for (int i = threadIdx.x; i < 12800; i += 256){
        unsigned v = m[i];
        if (v > 1u) not_i32 = 1;
        if (v != 0u && v != 0x3F800000u) not_f32 = 1;
    }
    __syncthreads();
    if (threadIdx.x == 0)
        g_mask_kind = (!not_i32) ? 1 : ((!not_f32) ? 2 : 0);
}

// ---------------- compaction: cnt -> scan -> scatter (parallel, deterministic) ----------------
__global__ void cnt_k(const void* __restrict__ mask){
    int bn = blockIdx.x * 256 + threadIdx.x;
    if (bn >= BNN) return;
    int s = 0;
    for (int j = 0; j < 50; j++) s += mask_at(mask, bn * 50 + j);
    g_cnt[bn] = (float)s;
    g_cnti[bn] = s;
}
__global__ void scan_k(){
    __shared__ int sh[BNN];
    int t = threadIdx.x;
    int v = g_cnti[t];
    sh[t] = v; __syncthreads();
    for (int d = 1; d < BNN; d <<= 1){
        int x = (t >= d) ? sh[t - d] : 0; __syncthreads();
        sh[t] += x; __syncthreads();
    }
    g_off[t] = sh[t] - v;
    if (t == BNN - 1) g_active = sh[t];
}
__global__ void scatter_k(const void* __restrict__ mask){
    int bn = blockIdx.x, t = threadIdx.x;    // 64 threads
    int m = (t < 50) ? mask_at(mask, bn * 50 + t) : 0;
    int w = t >> 5, lane = t & 31;
    unsigned bal = __ballot_sync(0xffffffffu, m);
    __shared__ int w0;
    if (t == 0) w0 = 0;
    __syncthreads();
    if (w == 0 && lane == 0) w0 = __popc(bal);
    __syncthreads();
    int pre = __popc(bal & ((1u << lane) - 1u)) + (w ? w0 : 0);
    if (m) g_ridx[g_off[bn] + pre] = bn * 50 + t;
}

// ---------------- pack kernels ----------------
__global__ void pack_A_k(const float* __restrict__ emb, const float* __restrict__ vis,
                         const float* __restrict__ bbox, const float* __restrict__ kp){
    int ci = blockIdx.x;
    if (ci >= g_active) return;
    int r = g_ridx[ci];
    for (int c = threadIdx.x; c < KP1; c += 256){
        float v;
        if (c < 2048)       v = emb[(size_t)r * 2048 + c];
        else if (c == 2048) v = vis[r];
        else if (c < 2053)  v = bbox[(size_t)r * 4 + (c - 2049)];
        else if (c < 2104)  v = kp[(size_t)r * 51 + (c - 2053)];
        else                v = 0.f;
        g_A[(size_t)ci * KP1 + c] = __float2half_rn(v);
    }
}
__global__ void pack_W1_k(const float* __restrict__ W1){
    uint32_t i = blockIdx.x * 256u + threadIdx.x;
    if (i >= (uint32_t)GP * KP1) return;
    uint32_t g = i / KP1, f = i % KP1;
    float v = (g < FEAT && f < FEAT) ? W1[(size_t)f * FEAT + g] : 0.f;
    g_W1T[i] = __float2half_rn(v);
}
__global__ void pack_W2_k(const float* __restrict__ W2){
    uint32_t i = blockIdx.x * 256u + threadIdx.x;
    if (i >= (uint32_t)TOK * GP) return;
    uint32_t t = i / GP, g = i % GP;
    float v = (g < FEAT) ? W2[(size_t)g * TOK + t] : 0.f;
    g_W2T[i] = __float2half_rn(v);
}
__global__ void round_hbar_k(){
    uint32_t i = blockIdx.x * 256u + threadIdx.x;
    if (i < (uint32_t)BNN * GP) g_hbh[i] = __float2half_rn(g_hbar[i]);
}

// ---------------- f16 mma.sync GEMM: CTA 128x128, K-chunk 32, 2-stage, ldmatrix ----------------
// smem tile: pitch 40 halves (80B); stage block = A(10240)+B(10240)=20480B, 2 stages
// MODE 0: g_A(compact) @ g_W1T^T -> relu(+b1), S-group reduce -> atomicAdd g_hbar (2-pass epi)
// MODE 1: g_hbh @ g_W2T^T -> (+cnt*b2)/50 -> outp
template<int MODE>
__global__ __launch_bounds__(256, 2) void gemm_tc(const float* __restrict__ bias,
                                                  float* __restrict__ outp){
    constexpr int LD  = (MODE == 0) ? KP1 : GP;
    constexpr int KCH = LD / 32;
    const __half* Aq = (MODE == 0) ? g_A   : g_hbh;
    const __half* Bq = (MODE == 0) ? g_W1T : g_W2T;

    int mtile = blockIdx.x, ntile = blockIdx.y;
    int active = (MODE == 0) ? g_active : BNN;
    if (mtile * 128 >= active) return;

    extern __shared__ char smem[];
    __shared__ int rbn[128];
    uint32_t sb = smem_u32(smem);

    int tid = threadIdx.x, wid = tid >> 5, lane = tid & 31;
    int warp_m = wid & 1, warp_n = wid >> 1;
    int g = lane >> 2, t4 = lane & 3;

    // staging: 2 threads per 64B row, 32B each
    int srow = tid >> 1, shalf = tid & 1;
    const __half* ag = Aq + (size_t)(mtile * 128 + srow) * LD + shalf * 16;
    const __half* bg = Bq + (size_t)(ntile * 128 + srow) * LD + shalf * 16;
    uint32_t s_off = (uint32_t)(srow * 80 + shalf * 32);

    float d[4][4][4];
    #pragma unroll
    for (int i = 0; i < 4; i++)
        #pragma unroll
        for (int j = 0; j < 4; j++)
            #pragma unroll
            for (int k = 0; k < 4; k++) d[i][j][k] = 0.f;

    // ldmatrix per-lane base addresses (byte offsets inside a stage block)
    // A: x4 -> a[mt][0..3]: mat = lane/8: row += (mat&1)*8, col += (mat>>1)*8 halves
    uint32_t a_base[4], b_base[2];
    {
        int arow_l = (lane & 7) + ((lane >> 3) & 1) * 8;
        int acol_b = ((lane >> 4) & 1) * 16;
        #pragma unroll
        for (int mt = 0; mt < 4; mt++)
            a_base[mt] = (uint32_t)((warp_m * 64 + mt * 16 + arow_l) * 80 + acol_b);
        int brow_l = (lane & 7) + ((lane >> 4) & 1) * 8;
        int bcol_b = ((lane >> 3) & 1) * 16;
        #pragma unroll
        for (int p = 0; p < 2; p++)
            b_base[p] = (uint32_t)(10240 + (warp_n * 32 + p * 16 + brow_l) * 80 + bcol_b);
    }

    {   // prologue: chunk 0 -> stage 0
        uint32_t sa = sb + s_off, sbb = sb + 10240 + s_off;
        #pragma unroll
        for (int j = 0; j < 2; j++){
            CP_ASYNC16(sa + j * 16, (const char*)ag + j * 16);
            CP_ASYNC16(sbb + j * 16, (const char*)bg + j * 16);
        }
        CP_COMMIT();
    }

    for (int c = 0; c < KCH; c++){
        int cur = c & 1;
        if (c + 1 < KCH){
            uint32_t off = ((c + 1) & 1) * 20480u;
            uint32_t sa = sb + off + s_off, sbb = sb + off + 10240 + s_off;
            const char* agc = (const char*)(ag + (c + 1) * 32);
            const char* bgc = (const char*)(bg + (c + 1) * 32);
            #pragma unroll
            for (int j = 0; j < 2; j++){
                CP_ASYNC16(sa + j * 16, agc + j * 16);
                CP_ASYNC16(sbb + j * 16, bgc + j * 16);
            }
            CP_COMMIT();
            CP_WAIT1();
        } else {
            CP_WAIT0();
        }
        __syncthreads();

        uint32_t stage = sb + cur * 20480u;
        #pragma unroll
        for (int s = 0; s < 2; s++){         // two k16 steps per 32-half chunk
            uint32_t so = stage + s * 32;
            uint32_t a[4][4], b[4][2];
            #pragma unroll
            for (int mt = 0; mt < 4; mt++)
                LDSM_X4(a[mt][0], a[mt][1], a[mt][2], a[mt][3], so + a_base[mt]);
            LDSM_X4(b[0][0], b[0][1], b[1][0], b[1][1], so + b_base[0]);
            LDSM_X4(b[2][0], b[2][1], b[3][0], b[3][1], so + b_base[1]);
            #pragma unroll
            for (int mt = 0; mt < 4; mt++)
                #pragma unroll
                for (int nt = 0; nt < 4; nt++) mma16(d[mt][nt], a[mt], b[nt]);
        }
        __syncthreads();
    }

    // ---------------- epilogue ----------------
    if (MODE == 0){
        float bv[4][2];
        #pragma unroll
        for (int nt = 0; nt < 4; nt++){
            int colg = ntile * 128 + warp_n * 32 + nt * 8 + 2 * t4;
            bv[nt][0] = (colg     < FEAT) ? bias[colg]     : 0.f;
            bv[nt][1] = (colg + 1 < FEAT) ? bias[colg + 1] : 0.f;
        }
        if (tid < 128){
            int idx = mtile * 128 + tid;
            rbn[tid] = (idx < active) ? (g_ridx[idx] / 50) : -1;
        }
        float* st = (float*)smem;  // 64 x 132 staging per pass (<= 33792 B)
        #pragma unroll
        for (int pass = 0; pass < 2; pass++){
            __syncthreads();
            if (warp_m == pass){
                #pragma unroll
                for (int mt = 0; mt < 4; mt++){
                    int rl = mt * 16 + g;   // local row within pass window
                    #pragma unroll
                    for (int nt = 0; nt < 4; nt++){
                        int cl = warp_n * 32 + nt * 8 + 2 * t4;
                        st[rl * 132 + cl]           = fmaxf(d[mt][nt][0] + bv[nt][0], 0.f);
                        st[rl * 132 + cl + 1]       = fmaxf(d[mt][nt][1] + bv[nt][1], 0.f);
                        st[(rl + 8) * 132 + cl]     = fmaxf(d[mt][nt][2] + bv[nt][0], 0.f);
                        st[(rl + 8) * 132 + cl + 1] = fmaxf(d[mt][nt][3] + bv[nt][1], 0.f);
                    }
                }
            }
            __syncthreads();
            int col = tid & 127, half = tid >> 7;
            int r0 = pass * 64 + half * 32, r1 = r0 + 32;
            int colg = ntile * 128 + col;
            float s = 0.f;
            int cur = rbn[r0];
            for (int r = r0; r < r1; r++){
                int b = rbn[r];
                if (b != cur){
                    if (cur >= 0) atomicAdd(&g_hbar[(size_t)cur * GP + colg], s);
                    s = 0.f; cur = b;
                }
                s += st[(r - pass * 64) * 132 + col];
            }
            if (cur >= 0) atomicAdd(&g_hbar[(size_t)cur * GP + colg], s);
        }
    } else {
        #pragma unroll
        for (int mt = 0; mt < 4; mt++){
            int rg = mtile * 128 + warp_m * 64 + mt * 16 + g;
            float cn0 = g_cnt[rg], cn8 = g_cnt[rg + 8];
            #pragma unroll
            for (int nt = 0; nt < 4; nt++){
                int cg = ntile * 128 + warp_n * 32 + nt * 8 + 2 * t4;
                float b0 = bias[cg], b1 = bias[cg + 1];
                *(float2*)(outp + (size_t)rg * TOK + cg) =
                    make_float2((d[mt][nt][0] + cn0 * b0) * 0.02f,
                                (d[mt][nt][1] + cn0 * b1) * 0.02f);
                *(float2*)(outp + (size_t)(rg + 8) * TOK + cg) =
                    make_float2((d[mt][nt][2] + cn8 * b0) * 0.02f,
                                (d[mt][nt][3] + cn8 * b1) * 0.02f);
            }
        }
    }
}

// ---------------- launch ----------------
extern "C" void kernel_launch(void* const* d_in, const int* in_sizes, int n_in,
                              void* d_out, int out_size){
    const float* emb  = (const float*)d_in[0];
    const float* vis  = (const float*)d_in[1];
    const float* bbox = (const float*)d_in[2];
    const float* kp   = (const float*)d_in[3];
    const void*  mask = d_in[4];
    const float* W1 = (const float*)d_in[5];
    const float* b1 = (const float*)d_in[6];
    const float* W2 = (const float*)d_in[7];
    const float* b2 = (const float*)d_in[8];
    float* out = (float*)d_out;

    void* hbar_ptr = nullptr;
    cudaGetSymbolAddress(&hbar_ptr, g_hbar);
    cudaFuncSetAttribute(gemm_tc<0>, cudaFuncAttributeMaxDynamicSharedMemorySize, SMEM_BYTES);
    cudaFuncSetAttribute(gemm_tc<1>, cudaFuncAttributeMaxDynamicSharedMemorySize, SMEM_BYTES);

    detect_mask_k<<<1, 256>>>((const unsigned*)mask);
    cnt_k    <<<(BNN + 255) / 256, 256>>>(mask);
    scan_k   <<<1, BNN>>>();
    scatter_k<<<BNN, 64>>>(mask);
    pack_A_k <<<MROWS, 256>>>(emb, vis, bbox, kp);
    pack_W1_k<<<((uint32_t)GP * KP1 + 255) / 256, 256>>>(W1);
    pack_W2_k<<<((uint32_t)TOK * GP + 255) / 256, 256>>>(W2);
    cudaMemsetAsync(hbar_ptr, 0, (size_t)BNN * GP * sizeof(float));

    gemm_tc<0><<<dim3(MROWS / 128, GP / 128), 256, SMEM_BYTES>>>(b1, nullptr);
    round_hbar_k<<<((uint32_t)BNN * GP + 255) / 256, 256>>>();
    gemm_tc<1><<<dim3(BNN / 128, TOK / 128), 256, SMEM_BYTES>>>(b2, out);
    (void)in_sizes; (void)n_in; (void)out_size;
}

// round 7
// speedup vs baseline: 2.6055x; 1.1101x over previous
#include <cuda_runtime.h>
#include <cuda_fp16.h>
#include <cstdint>
#include <cstddef>

// ---------------- sizes ----------------
#define MROWS 51200   // B*N*S
#define FEAT  2104
#define KP1   2176    // padded K for GEMM1 (68*32)
#define GP    2304    // padded hidden (72*32, 18*128)
#define KCHE  66      // effective K chunks: 66*32 = 2112 >= 2104 (rest all-zero)
#define NT1   17      // effective GEMM1 n-tiles: 17*128 = 2176 >= 2104
#define TOK   1024
#define BNN   1024
#define SMEM_BYTES 40960   // 2 stages * (A 10240 + B 10240); epilogue reuses (<= 33792)

// ---------------- scratch ----------------
__device__ __half g_A   [(size_t)MROWS * KP1];
__device__ __half g_W1T [(size_t)GP    * KP1];
__device__ __half g_W2T [(size_t)TOK   * GP];
__device__ __half g_hbh [(size_t)BNN   * GP];
__device__ float  g_hbar[(size_t)BNN   * GP];
__device__ float  g_cnt [BNN];
__device__ int    g_off [BNN];
__device__ int    g_ridx[MROWS];
__device__ int    g_active;
__device__ int    g_mask_kind;   // 0=int8/bool, 1=int32, 2=float32

// ---------------- helpers ----------------
__device__ __forceinline__ uint32_t smem_u32(const void* p){
    uint32_t a;
    asm("{ .reg .u64 t; cvta.to.shared.u64 t, %1; cvt.u32.u64 %0, t; }" : "=r"(a) : "l"(p));
    return a;
}
__device__ __forceinline__ int mask_at(const void* m, int i){
    int k = g_mask_kind;
    if (k == 0) return ((const unsigned char*)m)[i] != 0;
    if (k == 1) return ((const int*)m)[i] != 0;
    return ((const float*)m)[i] != 0.f;
}
__device__ __forceinline__ uint32_t h2u(float a, float b){
    __half2 h = __floats2half2_rn(a, b);
    return *(uint32_t*)&h;
}
#define CP_ASYNC16(s, g) asm volatile("cp.async.cg.shared.global [%0], [%1], 16;" :: "r"(s), "l"(g) : "memory")
#define CP_COMMIT()      asm volatile("cp.async.commit_group;" ::: "memory")
#define CP_WAIT0()       asm volatile("cp.async.wait_group 0;" ::: "memory")
#define LDSM_X4(r0,r1,r2,r3,addr) \
    asm volatile("ldmatrix.sync.aligned.m8n8.x4.shared.b16 {%0,%1,%2,%3}, [%4];" \
        : "=r"(r0), "=r"(r1), "=r"(r2), "=r"(r3) : "r"(addr))

// m16n8k16 f16 -> f32
__device__ __forceinline__ void mma16(float* d, const uint32_t* a, const uint32_t* b){
    asm volatile(
        "mma.sync.aligned.m16n8k16.row.col.f32.f16.f16.f32 "
        "{%0,%1,%2,%3}, {%4,%5,%6,%7}, {%8,%9}, {%0,%1,%2,%3};"
        : "+f"(d[0]), "+f"(d[1]), "+f"(d[2]), "+f"(d[3])
        : "r"(a[0]), "r"(a[1]), "r"(a[2]), "r"(a[3]), "r"(b[0]), "r"(b[1]));
}

// ---------------- prep: mask-dtype detect + per-bn count + scan (one block) ----------------
__global__ void prep_k(const unsigned* __restrict__ mw, const void* __restrict__ mask){
    __shared__ int n32, nf32;
    __shared__ int sh[BNN];
    int t = threadIdx.x;   // 1024
    if (t == 0){ n32 = 0; nf32 = 0; }
    __syncthreads();
    for (int i = t; i < 12800; i += 1024){
        unsigned v = mw[i];
        if (v > 1u) n32 = 1;
        if (v != 0u && v != 0x3F800000u) nf32 = 1;
    }
    __syncthreads();
    if (t == 0) g_mask_kind = (!n32) ? 1 : ((!nf32) ? 2 : 0);
    __syncthreads();
    int s = 0;
    for (int j = 0; j < 50; j++) s += mask_at(mask, t * 50 + j);
    g_cnt[t] = (float)s;
    sh[t] = s; __syncthreads();
    for (int d = 1; d < BNN; d <<= 1){
        int x = (t >= d) ? sh[t - d] : 0; __syncthreads();
        sh[t] += x; __syncthreads();
    }
    g_off[t] = sh[t] - s;
    if (t == BNN - 1) g_active = sh[t];
}
__global__ void scatter_k(const void* __restrict__ mask){
    int bn = blockIdx.x, t = threadIdx.x;    // 64 threads
    int m = (t < 50) ? mask_at(mask, bn * 50 + t) : 0;
    int w = t >> 5, lane = t & 31;
    unsigned bal = __ballot_sync(0xffffffffu, m);
    __shared__ int w0;
    if (t == 0) w0 = 0;
    __syncthreads();
    if (w == 0 && lane == 0) w0 = __popc(bal);
    __syncthreads();
    int pre = __popc(bal & ((1u << lane) - 1u)) + (w ? w0 : 0);
    if (m) g_ridx[g_off[bn] + pre] = bn * 50 + t;
}

// ---------------- pack kernels ----------------
__global__ void pack_A_k(const float* __restrict__ emb, const float* __restrict__ vis,
                         const float* __restrict__ bbox, const float* __restrict__ kp){
    int ci = blockIdx.x;
    if (ci >= g_active) return;
    int r = g_ridx[ci];
    int t = threadIdx.x;   // 256
    const float4* e4 = (const float4*)(emb + (size_t)r * 2048);
    uint4* dst = (uint4*)(g_A + (size_t)ci * KP1);
    {   // cols 0..2047: 256 groups of 8
        float4 v0 = e4[t * 2], v1 = e4[t * 2 + 1];
        uint4 o;
        o.x = h2u(v0.x, v0.y); o.y = h2u(v0.z, v0.w);
        o.z = h2u(v1.x, v1.y); o.w = h2u(v1.z, v1.w);
        dst[t] = o;
    }
    if (t < 128){   // cols 2048..2175 (tail + pad)
        int c = 2048 + t;
        float v;
        if (c == 2048)      v = vis[r];
        else if (c < 2053)  v = bbox[(size_t)r * 4 + (c - 2049)];
        else if (c < 2104)  v = kp[(size_t)r * 51 + (c - 2053)];
        else                v = 0.f;
        g_A[(size_t)ci * KP1 + c] = __float2half_rn(v);
    }
}
// tiled transpose: W1[f][g] (row-major) -> g_W1T[g][f] f16
__global__ void pack_W1_k(const float* __restrict__ W1){
    __shared__ float tile[32][33];
    int fb = blockIdx.x * 32, gb = blockIdx.y * 32;
    int tx = threadIdx.x, ty = threadIdx.y;   // 32 x 8
    #pragma unroll
    for (int i = 0; i < 4; i++){
        int f = fb + ty + i * 8, g = gb + tx;
        float v = (f < FEAT && g < FEAT) ? W1[(size_t)f * FEAT + g] : 0.f;
        tile[ty + i * 8][tx] = v;
    }
    __syncthreads();
    #pragma unroll
    for (int i = 0; i < 4; i++){
        int g = gb + ty + i * 8, f = fb + tx;
        if (g < GP && f < KP1)
            g_W1T[(size_t)g * KP1 + f] = __float2half_rn(tile[tx][ty + i * 8]);
    }
}
__global__ void pack_W2_k(const float* __restrict__ W2){
    uint32_t i = blockIdx.x * 256u + threadIdx.x;
    if (i >= (uint32_t)TOK * GP) return;
    uint32_t t = i / GP, g = i % GP;
    float v = (g < FEAT) ? W2[(size_t)g * TOK + t] : 0.f;
    g_W2T[i] = __float2half_rn(v);
}
__global__ void round_hbar_k(){
    uint32_t i = blockIdx.x * 256u + threadIdx.x;
    if (i < (uint32_t)BNN * GP) g_hbh[i] = __float2half_rn(g_hbar[i]);
}

// ---------------- f16 mma.sync GEMM: CTA 128x128, K-chunk 32, 2-stage, ldmatrix, 1 sync/chunk --
// MODE 0: g_A(compact) @ g_W1T^T -> relu(+b1), S-group reduce -> atomicAdd g_hbar (2-pass epi)
// MODE 1: g_hbh @ g_W2T^T -> (+cnt*b2)/50 -> outp
template<int MODE>
__global__ __launch_bounds__(256, 2) void gemm_tc(const float* __restrict__ bias,
                                                  float* __restrict__ outp){
    constexpr int LD = (MODE == 0) ? KP1 : GP;
    const __half* Aq = (MODE == 0) ? g_A   : g_hbh;
    const __half* Bq = (MODE == 0) ? g_W1T : g_W2T;

    int mtile = blockIdx.x, ntile = blockIdx.y;
    int active = (MODE == 0) ? g_active : BNN;
    if (mtile * 128 >= active) return;

    extern __shared__ char smem[];
    __shared__ int rbn[128];
    uint32_t sb = smem_u32(smem);

    int tid = threadIdx.x, wid = tid >> 5, lane = tid & 31;
    int warp_m = wid & 1, warp_n = wid >> 1;
    int g = lane >> 2, t4 = lane & 3;

    // staging: 2 threads per 64B row, 32B each
    int srow = tid >> 1, shalf = tid & 1;
    const __half* ag = Aq + (size_t)(mtile * 128 + srow) * LD + shalf * 16;
    const __half* bg = Bq + (size_t)(ntile * 128 + srow) * LD + shalf * 16;
    uint32_t s_off = (uint32_t)(srow * 80 + shalf * 32);

    float d[4][4][4];
    #pragma unroll
    for (int i = 0; i < 4; i++)
        #pragma unroll
        for (int j = 0; j < 4; j++)
            #pragma unroll
            for (int k = 0; k < 4; k++) d[i][j][k] = 0.f;

    uint32_t a_base[4], b_base[2];
    {
        int arow_l = (lane & 7) + ((lane >> 3) & 1) * 8;
        int acol_b = ((lane >> 4) & 1) * 16;
        #pragma unroll
        for (int mt = 0; mt < 4; mt++)
            a_base[mt] = (uint32_t)((warp_m * 64 + mt * 16 + arow_l) * 80 + acol_b);
        int brow_l = (lane & 7) + ((lane >> 4) & 1) * 8;
        int bcol_b = ((lane >> 3) & 1) * 16;
        #pragma unroll
        for (int p = 0; p < 2; p++)
            b_base[p] = (uint32_t)(10240 + (warp_n * 32 + p * 16 + brow_l) * 80 + bcol_b);
    }

    {   // prologue: chunk 0 -> stage 0
        uint32_t sa = sb + s_off, sbb = sb + 10240 + s_off;
        #pragma unroll
        for (int j = 0; j < 2; j++){
            CP_ASYNC16(sa + j * 16, (const char*)ag + j * 16);
            CP_ASYNC16(sbb + j * 16, (const char*)bg + j * 16);
        }
        CP_COMMIT();
    }

    for (int c = 0; c < KCHE; c++){
        CP_WAIT0();
        __syncthreads();                       // buf[c&1] ready; prev readers of buf[(c+1)&1] done
        if (c + 1 < KCHE){                     // issue next AFTER the sync -> no trailing barrier
            uint32_t off = ((c + 1) & 1) * 20480u;
            uint32_t sa = sb + off + s_off, sbb = sb + off + 10240 + s_off;
            const char* agc = (const char*)(ag + (c + 1) * 32);
            const char* bgc = (const char*)(bg + (c + 1) * 32);
            #pragma unroll
            for (int j = 0; j < 2; j++){
                CP_ASYNC16(sa + j * 16, agc + j * 16);
                CP_ASYNC16(sbb + j * 16, bgc + j * 16);
            }
            CP_COMMIT();
        }
        uint32_t stage = sb + (c & 1) * 20480u;
        #pragma unroll
        for (int s = 0; s < 2; s++){
            uint32_t so = stage + s * 32;
            uint32_t a[4][4], b[4][2];
            #pragma unroll
            for (int mt = 0; mt < 4; mt++)
                LDSM_X4(a[mt][0], a[mt][1], a[mt][2], a[mt][3], so + a_base[mt]);
            LDSM_X4(b[0][0], b[0][1], b[1][0], b[1][1], so + b_base[0]);
            LDSM_X4(b[2][0], b[2][1], b[3][0], b[3][1], so + b_base[1]);
            #pragma unroll
            for (int mt = 0; mt < 4; mt++)
                #pragma unroll
                for (int nt = 0; nt < 4; nt++) mma16(d[mt][nt], a[mt], b[nt]);
        }
    }

    // ---------------- epilogue ----------------
    if (MODE == 0){
        float bv[4][2];
        #pragma unroll
        for (int nt = 0; nt < 4; nt++){
            int colg = ntile * 128 + warp_n * 32 + nt * 8 + 2 * t4;
            bv[nt][0] = (colg     < FEAT) ? bias[colg]     : 0.f;
            bv[nt][1] = (colg + 1 < FEAT) ? bias[colg + 1] : 0.f;
        }
        if (tid < 128){
            int idx = mtile * 128 + tid;
            rbn[tid] = (idx < active) ? (g_ridx[idx] / 50) : -1;
        }
        float* st = (float*)smem;  // 64 x 132 staging per pass (<= 33792 B)
        #pragma unroll
        for (int pass = 0; pass < 2; pass++){
            __syncthreads();
            if (warp_m == pass){
                #pragma unroll
                for (int mt = 0; mt < 4; mt++){
                    int rl = mt * 16 + g;
                    #pragma unroll
                    for (int nt = 0; nt < 4; nt++){
                        int cl = warp_n * 32 + nt * 8 + 2 * t4;
                        st[rl * 132 + cl]           = fmaxf(d[mt][nt][0] + bv[nt][0], 0.f);
                        st[rl * 132 + cl + 1]       = fmaxf(d[mt][nt][1] + bv[nt][1], 0.f);
                        st[(rl + 8) * 132 + cl]     = fmaxf(d[mt][nt][2] + bv[nt][0], 0.f);
                        st[(rl + 8) * 132 + cl + 1] = fmaxf(d[mt][nt][3] + bv[nt][1], 0.f);
                    }
                }
            }
            __syncthreads();
            int col = tid & 127, half = tid >> 7;
            int r0 = pass * 64 + half * 32, r1 = r0 + 32;
            int colg = ntile * 128 + col;
            float s = 0.f;
            int cur = rbn[r0];
            for (int r = r0; r < r1; r++){
                int b = rbn[r];
                if (b != cur){
                    if (cur >= 0) atomicAdd(&g_hbar[(size_t)cur * GP + colg], s);
                    s = 0.f; cur = b;
                }
                s += st[(r - pass * 64) * 132 + col];
            }
            if (cur >= 0) atomicAdd(&g_hbar[(size_t)cur * GP + colg], s);
        }
    } else {
        #pragma unroll
        for (int mt = 0; mt < 4; mt++){
            int rg = mtile * 128 + warp_m * 64 + mt * 16 + g;
            float cn0 = g_cnt[rg], cn8 = g_cnt[rg + 8];
            #pragma unroll
            for (int nt = 0; nt < 4; nt++){
                int cg = ntile * 128 + warp_n * 32 + nt * 8 + 2 * t4;
                float b0 = bias[cg], b1 = bias[cg + 1];
                *(float2*)(outp + (size_t)rg * TOK + cg) =
                    make_float2((d[mt][nt][0] + cn0 * b0) * 0.02f,
                                (d[mt][nt][1] + cn0 * b1) * 0.02f);
                *(float2*)(outp + (size_t)(rg + 8) * TOK + cg) =
                    make_float2((d[mt][nt][2] + cn8 * b0) * 0.02f,
                                (d[mt][nt][3] + cn8 * b1) * 0.02f);
            }
        }
    }
}

// ---------------- launch ----------------
extern "C" void kernel_launch(void* const* d_in, const int* in_sizes, int n_in,
                              void* d_out, int out_size){
    const float* emb  = (const float*)d_in[0];
    const float* vis  = (const float*)d_in[1];
    const float* bbox = (const float*)d_in[2];
    const float* kp   = (const float*)d_in[3];
    const void*  mask = d_in[4];
    const float* W1 = (const float*)d_in[5];
    const float* b1 = (const float*)d_in[6];
    const float* W2 = (const float*)d_in[7];
    const float* b2 = (const float*)d_in[8];
    float* out = (float*)d_out;

    void* hbar_ptr = nullptr;
    cudaGetSymbolAddress(&hbar_ptr, g_hbar);
    cudaFuncSetAttribute(gemm_tc<0>, cudaFuncAttributeMaxDynamicSharedMemorySize, SMEM_BYTES);
    cudaFuncSetAttribute(gemm_tc<1>, cudaFuncAttributeMaxDynamicSharedMemorySize, SMEM_BYTES);

    prep_k   <<<1, 1024>>>((const unsigned*)mask, mask);
    scatter_k<<<BNN, 64>>>(mask);
    pack_A_k <<<MROWS, 256>>>(emb, vis, bbox, kp);
    pack_W1_k<<<dim3(KP1 / 32, GP / 32), dim3(32, 8)>>>(W1);
    pack_W2_k<<<((uint32_t)TOK * GP + 255) / 256, 256>>>(W2);
    cudaMemsetAsync(hbar_ptr, 0, (size_t)BNN * GP * sizeof(float));

    gemm_tc<0><<<dim3(MROWS / 128, NT1), 256, SMEM_BYTES>>>(b1, nullptr);
    round_hbar_k<<<((uint32_t)BNN * GP + 255) / 256, 256>>>();
    gemm_tc<1><<<dim3(BNN / 128, TOK / 128), 256, SMEM_BYTES>>>(b2, out);
    (void)in_sizes; (void)n_in; (void)out_size;
}

// round 8
// speedup vs baseline: 2.6917x; 1.0331x over previous
#include <cuda_runtime.h>
#include <cuda_fp16.h>
#include <cstdint>
#include <cstddef>

// ---------------- sizes ----------------
#define MROWS 51200   // B*N*S
#define FEAT  2104
#define KP1   2176    // padded K for GEMM1 (68*32)
#define GP    2304    // padded hidden (72*32, 18*128)
#define KCHE  66      // effective K chunks: 66*32 = 2112 >= 2104 (rest all-zero)
#define NT1   17      // effective GEMM1 n-tiles: 17*128 = 2176 >= 2104
#define TOK   1024
#define BNN   1024
#define SMEM_BYTES 40960   // 2 stages * (A 10240 + B 10240); epilogue reuses (<= 33792)

// ---------------- scratch ----------------
__device__ __half g_A   [(size_t)MROWS * KP1];
__device__ __half g_W1T [(size_t)GP    * KP1];
__device__ __half g_W2T [(size_t)TOK   * GP];
__device__ __half g_hbh [(size_t)BNN   * GP];
__device__ float  g_hbar[(size_t)BNN   * GP];
__device__ float  g_cnt [BNN];
__device__ int    g_off [BNN];
__device__ int    g_ridx[MROWS];
__device__ int    g_active;
__device__ int    g_mask_kind;   // 0=int8/bool, 1=int32, 2=float32

// ---------------- helpers ----------------
__device__ __forceinline__ uint32_t smem_u32(const void* p){
    uint32_t a;
    asm("{ .reg .u64 t; cvta.to.shared.u64 t, %1; cvt.u32.u64 %0, t; }" : "=r"(a) : "l"(p));
    return a;
}
__device__ __forceinline__ int mask_at(const void* m, int i){
    int k = g_mask_kind;
    if (k == 0) return ((const unsigned char*)m)[i] != 0;
    if (k == 1) return ((const int*)m)[i] != 0;
    return ((const float*)m)[i] != 0.f;
}
__device__ __forceinline__ uint32_t h2u(float a, float b){
    __half2 h = __floats2half2_rn(a, b);
    return *(uint32_t*)&h;
}
#define CP_ASYNC16(s, g) asm volatile("cp.async.cg.shared.global [%0], [%1], 16;" :: "r"(s), "l"(g) : "memory")
#define CP_COMMIT()      asm volatile("cp.async.commit_group;" ::: "memory")
#define CP_WAIT0()       asm volatile("cp.async.wait_group 0;" ::: "memory")
#define LDSM_X4(r0,r1,r2,r3,addr) \
    asm volatile("ldmatrix.sync.aligned.m8n8.x4.shared.b16 {%0,%1,%2,%3}, [%4];" \
        : "=r"(r0), "=r"(r1), "=r"(r2), "=r"(r3) : "r"(addr))

// m16n8k16 f16 -> f32
__device__ __forceinline__ void mma16(float* d, const uint32_t* a, const uint32_t* b){
    asm volatile(
        "mma.sync.aligned.m16n8k16.row.col.f32.f16.f16.f32 "
        "{%0,%1,%2,%3}, {%4,%5,%6,%7}, {%8,%9}, {%0,%1,%2,%3};"
        : "+f"(d[0]), "+f"(d[1]), "+f"(d[2]), "+f"(d[3])
        : "r"(a[0]), "r"(a[1]), "r"(a[2]), "r"(a[3]), "r"(b[0]), "r"(b[1]));
}

// ---------------- prep: mask-dtype detect + per-bn count + scan (one block) ----------------
__global__ void prep_k(const unsigned* __restrict__ mw, const void* __restrict__ mask){
    __shared__ int n32, nf32;
    __shared__ int sh[BNN];
    int t = threadIdx.x;   // 1024
    if (t == 0){ n32 = 0; nf32 = 0; }
    __syncthreads();
    for (int i = t; i < 12800; i += 1024){
        unsigned v = mw[i];
        if (v > 1u) n32 = 1;
        if (v != 0u && v != 0x3F800000u) nf32 = 1;
    }
    __syncthreads();
    if (t == 0) g_mask_kind = (!n32) ? 1 : ((!nf32) ? 2 : 0);
    __syncthreads();
    int s = 0;
    for (int j = 0; j < 50; j++) s += mask_at(mask, t * 50 + j);
    g_cnt[t] = (float)s;
    sh[t] = s; __syncthreads();
    for (int d = 1; d < BNN; d <<= 1){
        int x = (t >= d) ? sh[t - d] : 0; __syncthreads();
        sh[t] += x; __syncthreads();
    }
    g_off[t] = sh[t] - s;
    if (t == BNN - 1) g_active = sh[t];
}
__global__ void scatter_k(const void* __restrict__ mask){
    int bn = blockIdx.x, t = threadIdx.x;    // 64 threads
    int m = (t < 50) ? mask_at(mask, bn * 50 + t) : 0;
    int w = t >> 5, lane = t & 31;
    unsigned bal = __ballot_sync(0xffffffffu, m);
    __shared__ int w0;
    if (t == 0) w0 = 0;
    __syncthreads();
    if (w == 0 && lane == 0) w0 = __popc(bal);
    __syncthreads();
    int pre = __popc(bal & ((1u << lane) - 1u)) + (w ? w0 : 0);
    if (m) g_ridx[g_off[bn] + pre] = bn * 50 + t;
}

// ---------------- pack kernels ----------------
__global__ void pack_A_k(const float* __restrict__ emb, const float* __restrict__ vis,
                         const float* __restrict__ bbox, const float* __restrict__ kp){
    int ci = blockIdx.x;
    if (ci >= g_active) return;
    int r = g_ridx[ci];
    int t = threadIdx.x;   // 256
    const float4* e4 = (const float4*)(emb + (size_t)r * 2048);
    uint4* dst = (uint4*)(g_A + (size_t)ci * KP1);
    {   // cols 0..2047: 256 groups of 8
        float4 v0 = e4[t * 2], v1 = e4[t * 2 + 1];
        uint4 o;
        o.x = h2u(v0.x, v0.y); o.y = h2u(v0.z, v0.w);
        o.z = h2u(v1.x, v1.y); o.w = h2u(v1.z, v1.w);
        dst[t] = o;
    }
    if (t < 128){   // cols 2048..2175 (tail + pad)
        int c = 2048 + t;
        float v;
        if (c == 2048)      v = vis[r];
        else if (c < 2053)  v = bbox[(size_t)r * 4 + (c - 2049)];
        else if (c < 2104)  v = kp[(size_t)r * 51 + (c - 2053)];
        else                v = 0.f;
        g_A[(size_t)ci * KP1 + c] = __float2half_rn(v);
    }
}
// tiled transpose: W1[f][g] (row-major) -> g_W1T[g][f] f16
__global__ void pack_W1_k(const float* __restrict__ W1){
    __shared__ float tile[32][33];
    int fb = blockIdx.x * 32, gb = blockIdx.y * 32;
    int tx = threadIdx.x, ty = threadIdx.y;   // 32 x 8
    #pragma unroll
    for (int i = 0; i < 4; i++){
        int f = fb + ty + i * 8, g = gb + tx;
        float v = (f < FEAT && g < FEAT) ? W1[(size_t)f * FEAT + g] : 0.f;
        tile[ty + i * 8][tx] = v;
    }
    __syncthreads();
    #pragma unroll
    for (int i = 0; i < 4; i++){
        int g = gb + ty + i * 8, f = fb + tx;
        if (g < GP && f < KP1)
            g_W1T[(size_t)g * KP1 + f] = __float2half_rn(tile[tx][ty + i * 8]);
    }
}
// tiled transpose: W2[g][t] (row-major, g<FEAT) -> g_W2T[t][g] f16
__global__ void pack_W2_k(const float* __restrict__ W2){
    __shared__ float tile[32][33];
    int gb = blockIdx.x * 32, tb = blockIdx.y * 32;
    int tx = threadIdx.x, ty = threadIdx.y;   // 32 x 8
    #pragma unroll
    for (int i = 0; i < 4; i++){
        int gg = gb + ty + i * 8, tt = tb + tx;
        float v = (gg < FEAT) ? W2[(size_t)gg * TOK + tt] : 0.f;
        tile[ty + i * 8][tx] = v;
    }
    __syncthreads();
    #pragma unroll
    for (int i = 0; i < 4; i++){
        int tt = tb + ty + i * 8, gg = gb + tx;
        g_W2T[(size_t)tt * GP + gg] = __float2half_rn(tile[tx][ty + i * 8]);
    }
}
__global__ void round_hbar_k(){
    uint32_t i = blockIdx.x * 256u + threadIdx.x;
    if (i < (uint32_t)BNN * GP) g_hbh[i] = __float2half_rn(g_hbar[i]);
}

// ---------------- f16 mma.sync GEMM: CTA 128x128, K-chunk 32, 2-stage, ldmatrix, 1 sync/chunk --
// grid: x = ntile (fast), y = mtile  -> A tiles stay L2-resident across the ntile sweep
// MODE 0: g_A(compact) @ g_W1T^T -> relu(+b1), S-group reduce -> atomicAdd g_hbar (2-pass epi)
// MODE 1: g_hbh @ g_W2T^T -> (+cnt*b2)/50 -> outp
template<int MODE>
__global__ __launch_bounds__(256, 2) void gemm_tc(const float* __restrict__ bias,
                                                  float* __restrict__ outp){
    constexpr int LD = (MODE == 0) ? KP1 : GP;
    const __half* Aq = (MODE == 0) ? g_A   : g_hbh;
    const __half* Bq = (MODE == 0) ? g_W1T : g_W2T;

    int ntile = blockIdx.x, mtile = blockIdx.y;
    int active = (MODE == 0) ? g_active : BNN;
    if (mtile * 128 >= active) return;

    extern __shared__ char smem[];
    __shared__ int rbn[128];
    uint32_t sb = smem_u32(smem);

    int tid = threadIdx.x, wid = tid >> 5, lane = tid & 31;
    int warp_m = wid & 1, warp_n = wid >> 1;
    int g = lane >> 2, t4 = lane & 3;

    // staging: 2 threads per 64B row, 32B each
    int srow = tid >> 1, shalf = tid & 1;
    const __half* ag = Aq + (size_t)(mtile * 128 + srow) * LD + shalf * 16;
    const __half* bg = Bq + (size_t)(ntile * 128 + srow) * LD + shalf * 16;
    uint32_t s_off = (uint32_t)(srow * 80 + shalf * 32);

    float d[4][4][4];
    #pragma unroll
    for (int i = 0; i < 4; i++)
        #pragma unroll
        for (int j = 0; j < 4; j++)
            #pragma unroll
            for (int k = 0; k < 4; k++) d[i][j][k] = 0.f;

    uint32_t a_base[4], b_base[2];
    {
        int arow_l = (lane & 7) + ((lane >> 3) & 1) * 8;
        int acol_b = ((lane >> 4) & 1) * 16;
        #pragma unroll
        for (int mt = 0; mt < 4; mt++)
            a_base[mt] = (uint32_t)((warp_m * 64 + mt * 16 + arow_l) * 80 + acol_b);
        int brow_l = (lane & 7) + ((lane >> 4) & 1) * 8;
        int bcol_b = ((lane >> 3) & 1) * 16;
        #pragma unroll
        for (int p = 0; p < 2; p++)
            b_base[p] = (uint32_t)(10240 + (warp_n * 32 + p * 16 + brow_l) * 80 + bcol_b);
    }

    {   // prologue: chunk 0 -> stage 0
        uint32_t sa = sb + s_off, sbb = sb + 10240 + s_off;
        #pragma unroll
        for (int j = 0; j < 2; j++){
            CP_ASYNC16(sa + j * 16, (const char*)ag + j * 16);
            CP_ASYNC16(sbb + j * 16, (const char*)bg + j * 16);
        }
        CP_COMMIT();
    }

    for (int c = 0; c < KCHE; c++){
        CP_WAIT0();
        __syncthreads();                       // buf[c&1] ready; prev readers of buf[(c+1)&1] done
        if (c + 1 < KCHE){                     // issue next AFTER the sync -> no trailing barrier
            uint32_t off = ((c + 1) & 1) * 20480u;
            uint32_t sa = sb + off + s_off, sbb = sb + off + 10240 + s_off;
            const char* agc = (const char*)(ag + (c + 1) * 32);
            const char* bgc = (const char*)(bg + (c + 1) * 32);
            #pragma unroll
            for (int j = 0; j < 2; j++){
                CP_ASYNC16(sa + j * 16, agc + j * 16);
                CP_ASYNC16(sbb + j * 16, bgc + j * 16);
            }
            CP_COMMIT();
        }
        uint32_t stage = sb + (c & 1) * 20480u;
        #pragma unroll
        for (int s = 0; s < 2; s++){
            uint32_t so = stage + s * 32;
            uint32_t a[4][4], b[4][2];
            #pragma unroll
            for (int mt = 0; mt < 4; mt++)
                LDSM_X4(a[mt][0], a[mt][1], a[mt][2], a[mt][3], so + a_base[mt]);
            LDSM_X4(b[0][0], b[0][1], b[1][0], b[1][1], so + b_base[0]);
            LDSM_X4(b[2][0], b[2][1], b[3][0], b[3][1], so + b_base[1]);
            #pragma unroll
            for (int mt = 0; mt < 4; mt++)
                #pragma unroll
                for (int nt = 0; nt < 4; nt++) mma16(d[mt][nt], a[mt], b[nt]);
        }
    }

    // ---------------- epilogue ----------------
    if (MODE == 0){
        float bv[4][2];
        #pragma unroll
        for (int nt = 0; nt < 4; nt++){
            int colg = ntile * 128 + warp_n * 32 + nt * 8 + 2 * t4;
            bv[nt][0] = (colg     < FEAT) ? bias[colg]     : 0.f;
            bv[nt][1] = (colg + 1 < FEAT) ? bias[colg + 1] : 0.f;
        }
        if (tid < 128){
            int idx = mtile * 128 + tid;
            rbn[tid] = (idx < active) ? (g_ridx[idx] / 50) : -1;
        }
        float* st = (float*)smem;  // 64 x 132 staging per pass (<= 33792 B)
        #pragma unroll
        for (int pass = 0; pass < 2; pass++){
            __syncthreads();
            if (warp_m == pass){
                #pragma unroll
                for (int mt = 0; mt < 4; mt++){
                    int rl = mt * 16 + g;
                    #pragma unroll
                    for (int nt = 0; nt < 4; nt++){
                        int cl = warp_n * 32 + nt * 8 + 2 * t4;
                        st[rl * 132 + cl]           = fmaxf(d[mt][nt][0] + bv[nt][0], 0.f);
                        st[rl * 132 + cl + 1]       = fmaxf(d[mt][nt][1] + bv[nt][1], 0.f);
                        st[(rl + 8) * 132 + cl]     = fmaxf(d[mt][nt][2] + bv[nt][0], 0.f);
                        st[(rl + 8) * 132 + cl + 1] = fmaxf(d[mt][nt][3] + bv[nt][1], 0.f);
                    }
                }
            }
            __syncthreads();
            int col = tid & 127, half = tid >> 7;
            int r0 = pass * 64 + half * 32, r1 = r0 + 32;
            int colg = ntile * 128 + col;
            float s = 0.f;
            int cur = rbn[r0];
            for (int r = r0; r < r1; r++){
                int b = rbn[r];
                if (b != cur){
                    if (cur >= 0) atomicAdd(&g_hbar[(size_t)cur * GP + colg], s);
                    s = 0.f; cur = b;
                }
                s += st[(r - pass * 64) * 132 + col];
            }
            if (cur >= 0) atomicAdd(&g_hbar[(size_t)cur * GP + colg], s);
        }
    } else {
        #pragma unroll
        for (int mt = 0; mt < 4; mt++){
            int rg = mtile * 128 + warp_m * 64 + mt * 16 + g;
            float cn0 = g_cnt[rg], cn8 = g_cnt[rg + 8];
            #pragma unroll
            for (int nt = 0; nt < 4; nt++){
                int cg = ntile * 128 + warp_n * 32 + nt * 8 + 2 * t4;
                float b0 = bias[cg], b1 = bias[cg + 1];
                *(float2*)(outp + (size_t)rg * TOK + cg) =
                    make_float2((d[mt][nt][0] + cn0 * b0) * 0.02f,
                                (d[mt][nt][1] + cn0 * b1) * 0.02f);
                *(float2*)(outp + (size_t)(rg + 8) * TOK + cg) =
                    make_float2((d[mt][nt][2] + cn8 * b0) * 0.02f,
                                (d[mt][nt][3] + cn8 * b1) * 0.02f);
            }
        }
    }
}

// ---------------- launch ----------------
extern "C" void kernel_launch(void* const* d_in, const int* in_sizes, int n_in,
                              void* d_out, int out_size){
    const float* emb  = (const float*)d_in[0];
    const float* vis  = (const float*)d_in[1];
    const float* bbox = (const float*)d_in[2];
    const float* kp   = (const float*)d_in[3];
    const void*  mask = d_in[4];
    const float* W1 = (const float*)d_in[5];
    const float* b1 = (const float*)d_in[6];
    const float* W2 = (const float*)d_in[7];
    const float* b2 = (const float*)d_in[8];
    float* out = (float*)d_out;

    void* hbar_ptr = nullptr;
    cudaGetSymbolAddress(&hbar_ptr, g_hbar);
    cudaFuncSetAttribute(gemm_tc<0>, cudaFuncAttributeMaxDynamicSharedMemorySize, SMEM_BYTES);
    cudaFuncSetAttribute(gemm_tc<1>, cudaFuncAttributeMaxDynamicSharedMemorySize, SMEM_BYTES);

    prep_k   <<<1, 1024>>>((const unsigned*)mask, mask);
    scatter_k<<<BNN, 64>>>(mask);
    pack_A_k <<<MROWS, 256>>>(emb, vis, bbox, kp);
    pack_W1_k<<<dim3(KP1 / 32, GP / 32), dim3(32, 8)>>>(W1);
    pack_W2_k<<<dim3(GP / 32, TOK / 32), dim3(32, 8)>>>(W2);
    cudaMemsetAsync(hbar_ptr, 0, (size_t)BNN * GP * sizeof(float));

    gemm_tc<0><<<dim3(NT1, MROWS / 128), 256, SMEM_BYTES>>>(b1, nullptr);
    round_hbar_k<<<((uint32_t)BNN * GP + 255) / 256, 256>>>();
    gemm_tc<1><<<dim3(TOK / 128, BNN / 128), 256, SMEM_BYTES>>>(b2, out);
    (void)in_sizes; (void)n_in; (void)out_size;
}